// round 13
// baseline (speedup 1.0000x reference)
#include <cuda_runtime.h>
#include <cuda_fp16.h>
#include <math.h>

#define NN 50000
#define IN_C 128
#define OUT_C 128
#define NE 1600000
#define TOT (NE + NN)
#define NPAD 50176          // 49 * 1024
#define NTILES 49
#define LDA 136             // half-elements per smem row (128 + 8 pad)
#define GEMM_BLOCKS 391     // ceil(NN/128)
#define DEG_BLOCKS 391

// ---------------- scratch (static device globals; no allocation allowed) ----
__device__ __half2 g_h2[(size_t)NN * 64];     // h in fp16: 12.8 MB, L2-resident
__device__ float g_as[NN];
__device__ float g_ad[NN];
__device__ int   g_deg[NPAD];
__device__ int   g_rowptr[NPAD + 1];
__device__ int   g_cursor[NN];
__device__ unsigned g_state[NTILES];          // decoupled-lookback: flag<<30 | sum
__device__ uint2 g_csr[TOT];                  // .x = src idx, .y = float bits of exp(e)

static __device__ __forceinline__ unsigned smem_u32(const void* p) {
    return (unsigned)__cvta_generic_to_shared(p);
}

// ---------------- K1: fused HMMA GEMM (blocks < GEMM_BLOCKS) + degree count -
__global__ __launch_bounds__(256, 2)
void k_gemm_deg(const float* __restrict__ x, const float* __restrict__ W,
                const float* __restrict__ a_src, const float* __restrict__ a_dst,
                const int4* __restrict__ dst4)
{
    const int t = threadIdx.x;

    if (blockIdx.x >= GEMM_BLOCKS) {
        // ---- degree role: grid-stride over edge quads ----
        const int nq = NE / 4;
        const int stride = DEG_BLOCKS * 256;
        for (int i = (blockIdx.x - GEMM_BLOCKS) * 256 + t; i < nq; i += stride) {
            int4 d = dst4[i];
            atomicAdd(&g_deg[d.x], 1);
            atomicAdd(&g_deg[d.y], 1);
            atomicAdd(&g_deg[d.z], 1);
            atomicAdd(&g_deg[d.w], 1);
        }
        return;
    }

    // ---- GEMM role ----
    extern __shared__ __half smh[];
    __half* As = smh;               // 128 x LDA
    __half* Ws = smh + 128 * LDA;   // 128 x LDA  (W[k][n] row-major)
    const int row0 = blockIdx.x * 128;

    const float4* Wg4 = (const float4*)W;
    #pragma unroll 4
    for (int i = t; i < 4096; i += 256) {
        int k = i >> 5, c = i & 31;
        float4 v = Wg4[i];
        __half2 p0 = __floats2half2_rn(v.x, v.y);
        __half2 p1 = __floats2half2_rn(v.z, v.w);
        uint2 pk; pk.x = *(unsigned*)&p0; pk.y = *(unsigned*)&p1;
        *(uint2*)&Ws[k * LDA + c * 4] = pk;
    }
    const float4* xg4 = (const float4*)x;
    #pragma unroll 4
    for (int i = t; i < 4096; i += 256) {
        int r = i >> 5, c = i & 31;
        float4 v = make_float4(0.f, 0.f, 0.f, 0.f);
        if (row0 + r < NN) v = xg4[(size_t)(row0 + r) * 32 + c];
        __half2 p0 = __floats2half2_rn(v.x, v.y);
        __half2 p1 = __floats2half2_rn(v.z, v.w);
        uint2 pk; pk.x = *(unsigned*)&p0; pk.y = *(unsigned*)&p1;
        *(uint2*)&As[r * LDA + c * 4] = pk;
    }
    __syncthreads();

    const int w = t >> 5, l = t & 31;
    float acc[16][4];
    #pragma unroll
    for (int nt = 0; nt < 16; nt++)
        #pragma unroll
        for (int q = 0; q < 4; q++) acc[nt][q] = 0.f;

    const unsigned a_base = smem_u32(&As[(w * 16 + (l & 15)) * LDA + ((l & 16) ? 8 : 0)]);
    const unsigned b_base = smem_u32(&Ws[(l & 15) * LDA + ((l & 16) ? 8 : 0)]);

    #pragma unroll
    for (int k = 0; k < 8; k++) {
        unsigned a0, a1, a2, a3;
        asm volatile("ldmatrix.sync.aligned.m8n8.x4.shared.b16 {%0,%1,%2,%3}, [%4];"
                     : "=r"(a0), "=r"(a1), "=r"(a2), "=r"(a3)
                     : "r"(a_base + k * 32));
        const unsigned bk = b_base + (unsigned)(k * 16 * LDA * 2);
        #pragma unroll
        for (int ntp = 0; ntp < 8; ntp++) {
            unsigned b0, b1, b2, b3;
            asm volatile("ldmatrix.sync.aligned.m8n8.x4.trans.shared.b16 {%0,%1,%2,%3}, [%4];"
                         : "=r"(b0), "=r"(b1), "=r"(b2), "=r"(b3)
                         : "r"(bk + ntp * 32));
            asm volatile("mma.sync.aligned.m16n8k16.row.col.f32.f16.f16.f32 "
                         "{%0,%1,%2,%3}, {%4,%5,%6,%7}, {%8,%9}, {%0,%1,%2,%3};"
                         : "+f"(acc[2*ntp][0]), "+f"(acc[2*ntp][1]),
                           "+f"(acc[2*ntp][2]), "+f"(acc[2*ntp][3])
                         : "r"(a0), "r"(a1), "r"(a2), "r"(a3), "r"(b0), "r"(b1));
            asm volatile("mma.sync.aligned.m16n8k16.row.col.f32.f16.f16.f32 "
                         "{%0,%1,%2,%3}, {%4,%5,%6,%7}, {%8,%9}, {%0,%1,%2,%3};"
                         : "+f"(acc[2*ntp+1][0]), "+f"(acc[2*ntp+1][1]),
                           "+f"(acc[2*ntp+1][2]), "+f"(acc[2*ntp+1][3])
                         : "r"(a0), "r"(a1), "r"(a2), "r"(a3), "r"(b2), "r"(b3));
        }
    }
    __syncthreads();

    // stage D (fp16) into As: row-major, conflict-free
    {
        const int g = l >> 2, m = l & 3;
        #pragma unroll
        for (int nt = 0; nt < 16; nt++) {
            __half2 lo = __floats2half2_rn(acc[nt][0], acc[nt][1]);
            __half2 hi = __floats2half2_rn(acc[nt][2], acc[nt][3]);
            *(unsigned*)&As[(w * 16 + g) * LDA + nt * 8 + 2 * m]     = *(unsigned*)&lo;
            *(unsigned*)&As[(w * 16 + g + 8) * LDA + nt * 8 + 2 * m] = *(unsigned*)&hi;
        }
    }
    __syncthreads();

    const float4 av = ((const float4*)a_src)[l];
    const float4 dv = ((const float4*)a_dst)[l];
    uint2* h2out = (uint2*)g_h2;
    #pragma unroll 1
    for (int r = 0; r < 16; r++) {
        int row = row0 + w * 16 + r;
        if (row >= NN) break;
        uint2 pk = *(uint2*)&As[(w * 16 + r) * LDA + l * 4];
        h2out[(size_t)row * 32 + l] = pk;
        float2 f01 = __half22float2(*(__half2*)&pk.x);
        float2 f23 = __half22float2(*(__half2*)&pk.y);
        float s = f01.x * av.x + f01.y * av.y + f23.x * av.z + f23.y * av.w;
        float d = f01.x * dv.x + f01.y * dv.y + f23.x * dv.z + f23.y * dv.w;
        #pragma unroll
        for (int off = 16; off > 0; off >>= 1) {
            s += __shfl_xor_sync(0xffffffffu, s, off);
            d += __shfl_xor_sync(0xffffffffu, d, off);
        }
        if (l == 0) { g_as[row] = s; g_ad[row] = d; }
    }
}

// ---------------- K2: single-kernel decoupled-lookback scan ------------------
// Self-loop "+1" folded into the load. Writes rowptr AND cursor.
// All 49 blocks co-reside (<< 148 SMs) so the lookback spin is deadlock-free.
__global__ __launch_bounds__(1024)
void k_scan(void)
{
    __shared__ int warp_sums[32];
    __shared__ int sh_prefix;
    const int b = blockIdx.x;
    const int t = threadIdx.x;
    const int gid = b * 1024 + t;
    const int lane = t & 31, wid = t >> 5;

    int v = g_deg[gid] + (gid < NN ? 1 : 0);
    int xi = v;
    #pragma unroll
    for (int off = 1; off < 32; off <<= 1) {
        int y = __shfl_up_sync(0xffffffffu, xi, off);
        if (lane >= off) xi += y;
    }
    if (lane == 31) warp_sums[wid] = xi;
    __syncthreads();
    if (wid == 0) {
        int s = warp_sums[lane];
        #pragma unroll
        for (int off = 1; off < 32; off <<= 1) {
            int y = __shfl_up_sync(0xffffffffu, s, off);
            if (lane >= off) s += y;
        }
        warp_sums[lane] = s;
    }
    __syncthreads();
    const int base = (wid > 0) ? warp_sums[wid - 1] : 0;
    const int excl = xi + base - v;
    const int tot  = warp_sums[31];

    if (wid == 0) {
        if (lane == 0) atomicExch(&g_state[b], (1u << 30) | (unsigned)tot);
        int prefix = 0;
        int idx = b - 1;
        while (idx >= 0) {
            const int look = idx - lane;
            const bool active = (look >= 0);
            unsigned s;
            do {
                s = active ? *(volatile unsigned*)&g_state[look] : (2u << 30);
            } while (__any_sync(0xffffffffu, (s >> 30) == 0u));
            const unsigned m2 = __ballot_sync(0xffffffffu, active && (s >> 30) >= 2u);
            int take;
            if (m2) {
                const int fl = __ffs(m2) - 1;   // nearest predecessor w/ inclusive
                take = (active && lane <= fl) ? (int)(s & 0x3fffffffu) : 0;
            } else {
                take = active ? (int)(s & 0x3fffffffu) : 0;
            }
            #pragma unroll
            for (int o = 16; o > 0; o >>= 1) take += __shfl_xor_sync(0xffffffffu, take, o);
            prefix += take;
            if (m2) break;
            idx -= 32;
        }
        if (lane == 0) {
            sh_prefix = prefix;
            atomicExch(&g_state[b], (2u << 30) | (unsigned)(prefix + tot));
        }
    }
    __syncthreads();

    const int rp = excl + sh_prefix;
    g_rowptr[gid] = rp;
    if (gid < NN) g_cursor[gid] = rp;
}

// ---------------- K3: scatter edges (2 per thread); store w = exp(leaky(e)) -
__global__ void k_scatter(const int* __restrict__ src, const int* __restrict__ dst)
{
    int i = (blockIdx.x * blockDim.x + threadIdx.x) * 2;
    if (i >= TOT) return;

    int s0, d0, s1 = -1, d1 = -1;
    if (i + 1 < NE) {
        int2 sp = *(const int2*)&src[i];
        int2 dp = *(const int2*)&dst[i];
        s0 = sp.x; d0 = dp.x; s1 = sp.y; d1 = dp.y;
    } else {
        s0 = (i < NE) ? src[i] : i - NE;
        d0 = (i < NE) ? dst[i] : i - NE;
        if (i + 1 < TOT) { s1 = i + 1 - NE; d1 = i + 1 - NE; }
    }

    float e0 = g_as[s0] + g_ad[d0];
    e0 = (e0 > 0.f) ? e0 : 0.2f * e0;
    float w0 = __expf(e0);
    if (s1 >= 0) {
        float e1 = g_as[s1] + g_ad[d1];
        e1 = (e1 > 0.f) ? e1 : 0.2f * e1;
        float w1 = __expf(e1);
        int p0 = atomicAdd(&g_cursor[d0], 1);
        int p1 = atomicAdd(&g_cursor[d1], 1);
        uint2 k0; k0.x = (unsigned)s0; k0.y = __float_as_uint(w0);
        uint2 k1; k1.x = (unsigned)s1; k1.y = __float_as_uint(w1);
        g_csr[p0] = k0;
        g_csr[p1] = k1;
    } else {
        int p0 = atomicAdd(&g_cursor[d0], 1);
        uint2 k0; k0.x = (unsigned)s0; k0.y = __float_as_uint(w0);
        g_csr[p0] = k0;
    }
}

// ---------------- K4: half-warp-per-destination aggregation (unroll 8) ------
__global__ __launch_bounds__(256)
void k_aggregate(const float* __restrict__ bias, float* __restrict__ out)
{
    const int gw = (blockIdx.x * blockDim.x + threadIdx.x) >> 4;  // dst node
    if (gw >= NN) return;
    const int lane = threadIdx.x & 15;
    const int start = g_rowptr[gw];
    const int end   = g_rowptr[gw + 1];

    const uint4* h4 = (const uint4*)g_h2;   // 16 uint4 per row (128 halves)
    float accA[8] = {0.f,0.f,0.f,0.f,0.f,0.f,0.f,0.f};
    float accB[8] = {0.f,0.f,0.f,0.f,0.f,0.f,0.f,0.f};
    float denA = 0.f, denB = 0.f;

    int j = start;
    for (; j + 8 <= end; j += 8) {
        uint2 c[8];
        uint4 u[8];
        #pragma unroll
        for (int q = 0; q < 8; q++) c[q] = g_csr[j + q];
        #pragma unroll
        for (int q = 0; q < 8; q++) u[q] = h4[(size_t)c[q].x * 16 + lane];
        #pragma unroll
        for (int q = 0; q < 8; q++) {
            const float wq = __uint_as_float(c[q].y);
            float2 p0 = __half22float2(*(__half2*)&u[q].x);
            float2 p1 = __half22float2(*(__half2*)&u[q].y);
            float2 p2 = __half22float2(*(__half2*)&u[q].z);
            float2 p3 = __half22float2(*(__half2*)&u[q].w);
            if (q & 1) {
                denB += wq;
                accB[0] += wq*p0.x; accB[1] += wq*p0.y; accB[2] += wq*p1.x; accB[3] += wq*p1.y;
                accB[4] += wq*p2.x; accB[5] += wq*p2.y; accB[6] += wq*p3.x; accB[7] += wq*p3.y;
            } else {
                denA += wq;
                accA[0] += wq*p0.x; accA[1] += wq*p0.y; accA[2] += wq*p1.x; accA[3] += wq*p1.y;
                accA[4] += wq*p2.x; accA[5] += wq*p2.y; accA[6] += wq*p3.x; accA[7] += wq*p3.y;
            }
        }
    }
    for (; j + 4 <= end; j += 4) {
        uint2 c[4];
        uint4 u[4];
        #pragma unroll
        for (int q = 0; q < 4; q++) c[q] = g_csr[j + q];
        #pragma unroll
        for (int q = 0; q < 4; q++) u[q] = h4[(size_t)c[q].x * 16 + lane];
        #pragma unroll
        for (int q = 0; q < 4; q++) {
            const float wq = __uint_as_float(c[q].y);
            float2 p0 = __half22float2(*(__half2*)&u[q].x);
            float2 p1 = __half22float2(*(__half2*)&u[q].y);
            float2 p2 = __half22float2(*(__half2*)&u[q].z);
            float2 p3 = __half22float2(*(__half2*)&u[q].w);
            if (q & 1) {
                denB += wq;
                accB[0] += wq*p0.x; accB[1] += wq*p0.y; accB[2] += wq*p1.x; accB[3] += wq*p1.y;
                accB[4] += wq*p2.x; accB[5] += wq*p2.y; accB[6] += wq*p3.x; accB[7] += wq*p3.y;
            } else {
                denA += wq;
                accA[0] += wq*p0.x; accA[1] += wq*p0.y; accA[2] += wq*p1.x; accA[3] += wq*p1.y;
                accA[4] += wq*p2.x; accA[5] += wq*p2.y; accA[6] += wq*p3.x; accA[7] += wq*p3.y;
            }
        }
    }
    for (; j < end; j++) {
        uint2 c0 = g_csr[j];
        const float wq = __uint_as_float(c0.y);
        uint4 u0 = h4[(size_t)c0.x * 16 + lane];
        float2 p0 = __half22float2(*(__half2*)&u0.x);
        float2 p1 = __half22float2(*(__half2*)&u0.y);
        float2 p2 = __half22float2(*(__half2*)&u0.z);
        float2 p3 = __half22float2(*(__half2*)&u0.w);
        denA += wq;
        accA[0] += wq*p0.x; accA[1] += wq*p0.y; accA[2] += wq*p1.x; accA[3] += wq*p1.y;
        accA[4] += wq*p2.x; accA[5] += wq*p2.y; accA[6] += wq*p3.x; accA[7] += wq*p3.y;
    }

    const float inv = 1.f / ((denA + denB) + 1e-16f);
    const float4 b0 = ((const float4*)bias)[2 * lane];
    const float4 b1 = ((const float4*)bias)[2 * lane + 1];
    float4 o0, o1;
    o0.x = fmaxf((accA[0] + accB[0]) * inv + b0.x, 0.f);
    o0.y = fmaxf((accA[1] + accB[1]) * inv + b0.y, 0.f);
    o0.z = fmaxf((accA[2] + accB[2]) * inv + b0.z, 0.f);
    o0.w = fmaxf((accA[3] + accB[3]) * inv + b0.w, 0.f);
    o1.x = fmaxf((accA[4] + accB[4]) * inv + b1.x, 0.f);
    o1.y = fmaxf((accA[5] + accB[5]) * inv + b1.y, 0.f);
    o1.z = fmaxf((accA[6] + accB[6]) * inv + b1.z, 0.f);
    o1.w = fmaxf((accA[7] + accB[7]) * inv + b1.w, 0.f);
    float4* out4 = (float4*)out;
    out4[(size_t)gw * 32 + 2 * lane]     = o0;
    out4[(size_t)gw * 32 + 2 * lane + 1] = o1;
}

// ---------------- launch -----------------------------------------------------
extern "C" void kernel_launch(void* const* d_in, const int* in_sizes, int n_in,
                              void* d_out, int out_size)
{
    const float* x     = (const float*)d_in[0];
    const float* W     = (const float*)d_in[1];
    const float* a_src = (const float*)d_in[2];
    const float* a_dst = (const float*)d_in[3];
    const float* bias  = (const float*)d_in[4];
    const int*   ei    = (const int*)d_in[5];
    const int*   src   = ei;
    const int*   dst   = ei + NE;
    float* out = (float*)d_out;

    const int gemm_smem = 2 * 128 * LDA * (int)sizeof(__half); // 69632
    cudaFuncSetAttribute(k_gemm_deg, cudaFuncAttributeMaxDynamicSharedMemorySize, gemm_smem);

    void* degp = nullptr;
    cudaGetSymbolAddress(&degp, g_deg);
    cudaMemsetAsync(degp, 0, NPAD * sizeof(int), 0);
    void* stp = nullptr;
    cudaGetSymbolAddress(&stp, g_state);
    cudaMemsetAsync(stp, 0, NTILES * sizeof(unsigned), 0);

    k_gemm_deg<<<GEMM_BLOCKS + DEG_BLOCKS, 256, gemm_smem>>>(x, W, a_src, a_dst,
                                                            (const int4*)dst);
    k_scan<<<NTILES, 1024>>>();
    k_scatter<<<((TOT + 1) / 2 + 255) / 256, 256>>>(src, dst);
    k_aggregate<<<(NN * 16 + 255) / 256, 256>>>(bias, out);
}